// round 2
// baseline (speedup 1.0000x reference)
#include <cuda_runtime.h>
#include <cuda_bf16.h>
#include <mma.h>

using namespace nvcuda;

#define BATCH 256
#define TSTEPS 512
#define IDIM 256
#define HDIM 1024
#define KDIM 1280              // HDIM + IDIM
#define GROWS 4096             // 4*HDIM packed gate rows

// CTA tiling for the step GEMM
#define MT 64                  // batch tile
#define NT 128                 // packed gate-row tile (= 32 hidden units * 4 gates)
#define KC 32                  // K slab (fp32)
#define KCP 36                 // padded K stride in smem (fp32 elems, mult of 4)
#define GLD 132                // fp32 epilogue tile leading dim

// ---------------- persistent device scratch (no allocations allowed) ---------
__device__ float g_Wpack[GROWS * KDIM];     // 21 MB, packed per-CTA row order
__device__ float g_BiasPack[GROWS];
__device__ float g_HX[2][BATCH * KDIM];     // [h | x_t] ping-pong, fp32
__device__ float g_C[BATCH * HDIM];         // cell state fp32

// Pack [w_hh | w_ih] rows into per-CTA-contiguous order + fold biases.
// Packed row p = j*128 + gate*32 + r  <->  original gate row g = gate*1024 + j*32 + r
__global__ void k_convert(const float* __restrict__ w_ih, const float* __restrict__ w_hh,
                          const float* __restrict__ b_ih, const float* __restrict__ b_hh) {
    int total = GROWS * KDIM;
    for (int idx = blockIdx.x * blockDim.x + threadIdx.x; idx < total;
         idx += gridDim.x * blockDim.x) {
        int p = idx / KDIM, k = idx - p * KDIM;
        int j = p >> 7, gate = (p >> 5) & 3, r = p & 31;
        int g = gate * HDIM + j * 32 + r;
        g_Wpack[idx] = (k < HDIM) ? w_hh[g * HDIM + k] : w_ih[g * IDIM + (k - HDIM)];
        if (k == 0) g_BiasPack[p] = b_ih[g] + b_hh[g];
    }
}

// h=0, c=0, stage x_0 into HX[0]
__global__ void k_init(const float* __restrict__ ts) {
    int idx = blockIdx.x * blockDim.x + threadIdx.x;
    if (idx >= BATCH * KDIM) return;
    int m = idx / KDIM, k = idx - m * KDIM;
    if (k < HDIM) {
        g_HX[0][idx] = 0.f;
        g_C[m * HDIM + k] = 0.f;
    } else {
        g_HX[0][idx] = ts[m * (TSTEPS * IDIM) + (k - HDIM)];
    }
}

__device__ __forceinline__ float sigmoidf_(float x) {
    return 1.f / (1.f + __expf(-x));
}

// One LSTM timestep: gates = HXr @ Wpack^T (tf32 wmma), fused cell update epilogue.
__global__ __launch_bounds__(256) void k_step(int t, const float* __restrict__ ts) {
    const float* __restrict__ HXr = g_HX[t & 1];
    float* __restrict__ HXw = g_HX[(t + 1) & 1];

    const int jt = blockIdx.x;        // 0..31  hidden-unit tile (32 units, 4 gates)
    const int mt = blockIdx.y;        // 0..3   batch tile
    const int m0 = mt * MT;
    const int p0 = jt * NT;

    extern __shared__ char smem[];
    float* As = (float*)smem;                       // [MT][KCP]
    float* Bs = As + MT * KCP;                      // [NT][KCP]
    float* Gs = (float*)smem;                       // [MT][GLD] (reuses A/B region)

    const int tid = threadIdx.x;
    const int wid = tid >> 5;
    const int warp_m = wid >> 2;      // 0..1
    const int warp_n = wid & 3;       // 0..3

    wmma::fragment<wmma::accumulator, 16, 16, 8, float> acc[2][2];
#pragma unroll
    for (int i = 0; i < 2; i++)
#pragma unroll
        for (int j = 0; j < 2; j++) wmma::fill_fragment(acc[i][j], 0.f);

    for (int kc = 0; kc < KDIM; kc += KC) {
        __syncthreads();
        // load A tile: 64 rows x 32 cols fp32 (8 x float4 per row)
#pragma unroll
        for (int u = tid; u < MT * 8; u += 256) {
            int row = u >> 3, c4 = u & 7;
            *(float4*)(As + row * KCP + c4 * 4) =
                *(const float4*)(HXr + (m0 + row) * KDIM + kc + c4 * 4);
        }
        // load B tile: 128 rows x 32 cols fp32
#pragma unroll
        for (int u = tid; u < NT * 8; u += 256) {
            int row = u >> 3, c4 = u & 7;
            *(float4*)(Bs + row * KCP + c4 * 4) =
                *(const float4*)(g_Wpack + (size_t)(p0 + row) * KDIM + kc + c4 * 4);
        }
        __syncthreads();

#pragma unroll
        for (int ko = 0; ko < KC; ko += 8) {
            wmma::fragment<wmma::matrix_a, 16, 16, 8, wmma::precision::tf32, wmma::row_major> af[2];
            wmma::fragment<wmma::matrix_b, 16, 16, 8, wmma::precision::tf32, wmma::col_major> bf[2];
#pragma unroll
            for (int i = 0; i < 2; i++) {
                wmma::load_matrix_sync(af[i], As + (warp_m * 32 + i * 16) * KCP + ko, KCP);
#pragma unroll
                for (int e = 0; e < af[i].num_elements; e++)
                    af[i].x[e] = wmma::__float_to_tf32(af[i].x[e]);
            }
#pragma unroll
            for (int j = 0; j < 2; j++) {
                wmma::load_matrix_sync(bf[j], Bs + (warp_n * 32 + j * 16) * KCP + ko, KCP);
#pragma unroll
                for (int e = 0; e < bf[j].num_elements; e++)
                    bf[j].x[e] = wmma::__float_to_tf32(bf[j].x[e]);
            }
#pragma unroll
            for (int i = 0; i < 2; i++)
#pragma unroll
                for (int j = 0; j < 2; j++)
                    wmma::mma_sync(acc[i][j], af[i], bf[j], acc[i][j]);
        }
    }
    __syncthreads();

    // spill gate tile to smem for the cross-gate epilogue
#pragma unroll
    for (int i = 0; i < 2; i++)
#pragma unroll
        for (int j = 0; j < 2; j++)
            wmma::store_matrix_sync(Gs + (warp_m * 32 + i * 16) * GLD + warp_n * 32 + j * 16,
                                    acc[i][j], GLD, wmma::mem_row_major);
    __syncthreads();

    // fused LSTM cell update: 64 batch x 32 hidden units
    for (int q = tid; q < MT * 32; q += 256) {
        int ml = q >> 5, hh = q & 31;
        float il = Gs[ml * GLD + hh]      + g_BiasPack[p0 + hh];
        float fl = Gs[ml * GLD + 32 + hh] + g_BiasPack[p0 + 32 + hh];
        float gl = Gs[ml * GLD + 64 + hh] + g_BiasPack[p0 + 64 + hh];
        float ol = Gs[ml * GLD + 96 + hh] + g_BiasPack[p0 + 96 + hh];
        float ig = sigmoidf_(il);
        float fg = sigmoidf_(fl);
        float gt = tanhf(gl);
        float og = sigmoidf_(ol);
        int m = m0 + ml;
        int hcol = jt * 32 + hh;
        float c = fg * g_C[m * HDIM + hcol] + ig * gt;
        g_C[m * HDIM + hcol] = c;
        HXw[m * KDIM + hcol] = og * tanhf(c);
    }

    // stage x_{t+1} into the write buffer (CTAs jt<8 cover the 256 input cols)
    if (t + 1 < TSTEPS && jt < 8) {
        for (int q = tid; q < MT * 32; q += 256) {
            int ml = q >> 5, cc = q & 31;
            int m = m0 + ml;
            int col = jt * 32 + cc;
            HXw[m * KDIM + HDIM + col] = ts[(m * TSTEPS + (t + 1)) * IDIM + col];
        }
    }
}

// out[m] = c[m,:] . fc_w + fc_b
__global__ void k_fc(const float* __restrict__ fc_w, const float* __restrict__ fc_b,
                     float* __restrict__ out) {
    int m = blockIdx.x;
    float s = 0.f;
    for (int k = threadIdx.x; k < HDIM; k += blockDim.x)
        s += g_C[m * HDIM + k] * fc_w[k];
#pragma unroll
    for (int o = 16; o; o >>= 1) s += __shfl_xor_sync(0xffffffffu, s, o);
    __shared__ float red[32];
    if ((threadIdx.x & 31) == 0) red[threadIdx.x >> 5] = s;
    __syncthreads();
    if (threadIdx.x < 32) {
        float v = (threadIdx.x < (int)(blockDim.x >> 5)) ? red[threadIdx.x] : 0.f;
#pragma unroll
        for (int o = 16; o; o >>= 1) v += __shfl_xor_sync(0xffffffffu, v, o);
        if (threadIdx.x == 0) out[m] = v + fc_b[0];
    }
}

extern "C" void kernel_launch(void* const* d_in, const int* in_sizes, int n_in,
                              void* d_out, int out_size) {
    (void)in_sizes; (void)n_in; (void)out_size;
    const float* ts   = (const float*)d_in[0];
    const float* w_ih = (const float*)d_in[1];
    const float* w_hh = (const float*)d_in[2];
    const float* b_ih = (const float*)d_in[3];
    const float* b_hh = (const float*)d_in[4];
    const float* fc_w = (const float*)d_in[5];
    const float* fc_b = (const float*)d_in[6];
    float* out = (float*)d_out;

    k_convert<<<512, 256>>>(w_ih, w_hh, b_ih, b_hh);
    k_init<<<(BATCH * KDIM + 255) / 256, 256>>>(ts);

    // smem: max( A+B = (MT+NT)*KCP*4 = 27648 , Gs = MT*GLD*4 = 33792 )
    const size_t smem = (size_t)MT * GLD * sizeof(float);
    dim3 grid(32, 4);
    for (int t = 0; t < TSTEPS; ++t)
        k_step<<<grid, 256, smem>>>(t, ts);

    k_fc<<<BATCH, 256>>>(fc_w, fc_b, out);
}

// round 3
// speedup vs baseline: 1.2907x; 1.2907x over previous
#include <cuda_runtime.h>
#include <cuda_bf16.h>
#include <mma.h>

using namespace nvcuda;

#define BATCH 256
#define TSTEPS 512
#define IDIM 256
#define HDIM 1024
#define KDIM 1280              // HDIM + IDIM
#define GROWS 4096             // 4*HDIM packed gate rows

// CTA tiling for the step GEMM
#define MT 64                  // batch tile
#define NT 128                 // packed gate-row tile (= 32 hidden units * 4 gates)
#define KC 64                  // K slab (fp32/tf32)
#define KCP 68                 // padded K stride in smem (fp32 elems, mult of 4)
#define GLD 132                // fp32 epilogue tile leading dim
#define NSLAB (KDIM / KC)      // 20
#define STAGE_ELEMS ((MT + NT) * KCP)          // 13056 floats
#define SMEM_BYTES (2 * STAGE_ELEMS * 4)       // 104448

// ---------------- persistent device scratch (no allocations allowed) ---------
__device__ float g_Wpack[GROWS * KDIM];     // 21 MB, packed + tf32-rounded
__device__ float g_BiasPack[GROWS];
__device__ float g_HX[2][BATCH * KDIM];     // [h | x_t] ping-pong, tf32-rounded fp32
__device__ float g_C[BATCH * HDIM];         // cell state fp32 (full precision)

__device__ __forceinline__ float tf32r(float x) {
    asm("cvt.rna.tf32.f32 %0, %0;" : "+f"(x));
    return x;
}

__device__ __forceinline__ void cp_async16(void* sptr, const void* gptr) {
    unsigned sa = (unsigned)__cvta_generic_to_shared(sptr);
    asm volatile("cp.async.cg.shared.global [%0], [%1], 16;\n" :: "r"(sa), "l"(gptr));
}
__device__ __forceinline__ void cp_commit() {
    asm volatile("cp.async.commit_group;\n");
}
template <int N>
__device__ __forceinline__ void cp_wait() {
    asm volatile("cp.async.wait_group %0;\n" :: "n"(N));
}

// Pack [w_hh | w_ih] rows into per-CTA-contiguous order, tf32-round, fold biases.
// Packed row p = j*128 + gate*32 + r  <->  original gate row g = gate*1024 + j*32 + r
__global__ void k_convert(const float* __restrict__ w_ih, const float* __restrict__ w_hh,
                          const float* __restrict__ b_ih, const float* __restrict__ b_hh) {
    int total = GROWS * KDIM;
    for (int idx = blockIdx.x * blockDim.x + threadIdx.x; idx < total;
         idx += gridDim.x * blockDim.x) {
        int p = idx / KDIM, k = idx - p * KDIM;
        int j = p >> 7, gate = (p >> 5) & 3, r = p & 31;
        int g = gate * HDIM + j * 32 + r;
        float v = (k < HDIM) ? w_hh[g * HDIM + k] : w_ih[g * IDIM + (k - HDIM)];
        g_Wpack[idx] = tf32r(v);
        if (k == 0) g_BiasPack[p] = b_ih[g] + b_hh[g];
    }
}

// h=0, c=0, stage x_0 (tf32-rounded) into HX[0]
__global__ void k_init(const float* __restrict__ ts) {
    int idx = blockIdx.x * blockDim.x + threadIdx.x;
    if (idx >= BATCH * KDIM) return;
    int m = idx / KDIM, k = idx - m * KDIM;
    if (k < HDIM) {
        g_HX[0][idx] = 0.f;
        g_C[m * HDIM + k] = 0.f;
    } else {
        g_HX[0][idx] = tf32r(ts[m * (TSTEPS * IDIM) + (k - HDIM)]);
    }
}

__device__ __forceinline__ float sigmoidf_(float x) {
    return 1.f / (1.f + __expf(-x));
}

// One LSTM timestep: gates = HXr @ Wpack^T (tf32 wmma, 2-stage cp.async pipeline),
// fused cell update epilogue.
__global__ __launch_bounds__(256, 1) void k_step(int t, const float* __restrict__ ts) {
    const float* __restrict__ HXr = g_HX[t & 1];
    float* __restrict__ HXw = g_HX[(t + 1) & 1];

    const int jt = blockIdx.x;        // 0..31  hidden-unit tile (32 units, 4 gates)
    const int mt = blockIdx.y;        // 0..3   batch tile
    const int m0 = mt * MT;
    const int p0 = jt * NT;

    extern __shared__ char smem[];
    float* Gs = (float*)smem;         // [MT][GLD] epilogue tile (aliases stage 0)

    const int tid = threadIdx.x;
    const int wid = tid >> 5;
    const int warp_m = wid >> 2;      // 0..1
    const int warp_n = wid & 3;       // 0..3

    wmma::fragment<wmma::accumulator, 16, 16, 8, float> acc[2][2];
#pragma unroll
    for (int i = 0; i < 2; i++)
#pragma unroll
        for (int j = 0; j < 2; j++) wmma::fill_fragment(acc[i][j], 0.f);

    // ---- async load of one K slab into a stage: A 64x64, B 128x64 (float4s) ----
    auto load_slab = [&](int s, int stg) {
        float* As = (float*)smem + stg * STAGE_ELEMS;
        float* Bs = As + MT * KCP;
        int kc = s * KC;
        // A: 64 rows x 16 float4 = 1024 ops / 256 thr = 4 each
#pragma unroll
        for (int u = tid; u < MT * 16; u += 256) {
            int row = u >> 4, c4 = u & 15;
            cp_async16(As + row * KCP + c4 * 4,
                       HXr + (m0 + row) * KDIM + kc + c4 * 4);
        }
        // B: 128 rows x 16 float4 = 2048 ops / 256 thr = 8 each
#pragma unroll
        for (int u = tid; u < NT * 16; u += 256) {
            int row = u >> 4, c4 = u & 15;
            cp_async16(Bs + row * KCP + c4 * 4,
                       g_Wpack + (size_t)(p0 + row) * KDIM + kc + c4 * 4);
        }
    };

    load_slab(0, 0);
    cp_commit();

    for (int s = 0; s < NSLAB; ++s) {
        const int stg = s & 1;
        if (s + 1 < NSLAB) {
            load_slab(s + 1, stg ^ 1);
            cp_commit();
            cp_wait<1>();
        } else {
            cp_wait<0>();
        }
        __syncthreads();

        const float* As = (const float*)smem + stg * STAGE_ELEMS;
        const float* Bs = As + MT * KCP;

#pragma unroll
        for (int ko = 0; ko < KC; ko += 8) {
            wmma::fragment<wmma::matrix_a, 16, 16, 8, wmma::precision::tf32, wmma::row_major> af[2];
            wmma::fragment<wmma::matrix_b, 16, 16, 8, wmma::precision::tf32, wmma::col_major> bf[2];
#pragma unroll
            for (int i = 0; i < 2; i++)
                wmma::load_matrix_sync(af[i], As + (warp_m * 32 + i * 16) * KCP + ko, KCP);
#pragma unroll
            for (int j = 0; j < 2; j++)
                wmma::load_matrix_sync(bf[j], Bs + (warp_n * 32 + j * 16) * KCP + ko, KCP);
#pragma unroll
            for (int i = 0; i < 2; i++)
#pragma unroll
                for (int j = 0; j < 2; j++)
                    wmma::mma_sync(acc[i][j], af[i], bf[j], acc[i][j]);
        }
        __syncthreads();
    }

    // spill gate tile to smem for the cross-gate epilogue
#pragma unroll
    for (int i = 0; i < 2; i++)
#pragma unroll
        for (int j = 0; j < 2; j++)
            wmma::store_matrix_sync(Gs + (warp_m * 32 + i * 16) * GLD + warp_n * 32 + j * 16,
                                    acc[i][j], GLD, wmma::mem_row_major);
    __syncthreads();

    // fused LSTM cell update: 64 batch x 32 hidden units
    for (int q = tid; q < MT * 32; q += 256) {
        int ml = q >> 5, hh = q & 31;
        float il = Gs[ml * GLD + hh]      + g_BiasPack[p0 + hh];
        float fl = Gs[ml * GLD + 32 + hh] + g_BiasPack[p0 + 32 + hh];
        float gl = Gs[ml * GLD + 64 + hh] + g_BiasPack[p0 + 64 + hh];
        float ol = Gs[ml * GLD + 96 + hh] + g_BiasPack[p0 + 96 + hh];
        float ig = sigmoidf_(il);
        float fg = sigmoidf_(fl);
        float gt = tanhf(gl);
        float og = sigmoidf_(ol);
        int m = m0 + ml;
        int hcol = jt * 32 + hh;
        float c = fg * g_C[m * HDIM + hcol] + ig * gt;
        g_C[m * HDIM + hcol] = c;
        HXw[m * KDIM + hcol] = tf32r(og * tanhf(c));
    }

    // stage x_{t+1} (tf32-rounded) into the write buffer (CTAs jt<8 cover 256 cols)
    if (t + 1 < TSTEPS && jt < 8) {
        for (int q = tid; q < MT * 32; q += 256) {
            int ml = q >> 5, cc = q & 31;
            int m = m0 + ml;
            int col = jt * 32 + cc;
            HXw[m * KDIM + HDIM + col] = tf32r(ts[(m * TSTEPS + (t + 1)) * IDIM + col]);
        }
    }
}

// out[m] = c[m,:] . fc_w + fc_b
__global__ void k_fc(const float* __restrict__ fc_w, const float* __restrict__ fc_b,
                     float* __restrict__ out) {
    int m = blockIdx.x;
    float s = 0.f;
    for (int k = threadIdx.x; k < HDIM; k += blockDim.x)
        s += g_C[m * HDIM + k] * fc_w[k];
#pragma unroll
    for (int o = 16; o; o >>= 1) s += __shfl_xor_sync(0xffffffffu, s, o);
    __shared__ float red[32];
    if ((threadIdx.x & 31) == 0) red[threadIdx.x >> 5] = s;
    __syncthreads();
    if (threadIdx.x < 32) {
        float v = (threadIdx.x < (int)(blockDim.x >> 5)) ? red[threadIdx.x] : 0.f;
#pragma unroll
        for (int o = 16; o; o >>= 1) v += __shfl_xor_sync(0xffffffffu, v, o);
        if (threadIdx.x == 0) out[m] = v + fc_b[0];
    }
}

extern "C" void kernel_launch(void* const* d_in, const int* in_sizes, int n_in,
                              void* d_out, int out_size) {
    (void)in_sizes; (void)n_in; (void)out_size;
    const float* ts   = (const float*)d_in[0];
    const float* w_ih = (const float*)d_in[1];
    const float* w_hh = (const float*)d_in[2];
    const float* b_ih = (const float*)d_in[3];
    const float* b_hh = (const float*)d_in[4];
    const float* fc_w = (const float*)d_in[5];
    const float* fc_b = (const float*)d_in[6];
    float* out = (float*)d_out;

    // non-stream attribute call: safe under graph capture, idempotent
    cudaFuncSetAttribute(k_step, cudaFuncAttributeMaxDynamicSharedMemorySize, SMEM_BYTES);

    k_convert<<<512, 256>>>(w_ih, w_hh, b_ih, b_hh);
    k_init<<<(BATCH * KDIM + 255) / 256, 256>>>(ts);

    dim3 grid(32, 4);
    for (int t = 0; t < TSTEPS; ++t)
        k_step<<<grid, 256, SMEM_BYTES>>>(t, ts);

    k_fc<<<BATCH, 256>>>(fc_w, fc_b, out);
}